// round 16
// baseline (speedup 1.0000x reference)
#include <cuda_runtime.h>
#include <cuda_bf16.h>
#include <cuda_fp16.h>
#include <cstdint>
#include <cstddef>

#define NMAX 50000
#define EMAX 800000
#define HDIM 128
#define NG 64
#define BN_EPS_F 1e-5f
#define SCAN_BLK 1024
#define MAXNB 64

// ---------------- scratch (static device globals; no runtime alloc) ----------
__device__ int   g_not64 = 0;          // sticky: 1 if int inputs are int32
__device__ int   g_deg[NMAX];
__device__ int   g_incl[NMAX];
__device__ int   g_bsum[MAXNB];
__device__ int   g_rowptr[NMAX + 1];
__device__ int   g_cursor[NMAX];
__device__ int   g_col[EMAX];
__device__ float g_dinv[NMAX];
__device__ __align__(16) __half g_yh[(size_t)NMAX * HDIM];   // ping
__device__ __align__(16) __half g_yh2[(size_t)NMAX * HDIM];  // pong
__device__ __align__(16) __half g_af[(size_t)NMAX * HDIM];   // h3 (fp16)
// conv1 split-bf16 planes
__device__ __align__(16) __nv_bfloat16 g_xh[(size_t)NMAX * 256];
__device__ __align__(16) __nv_bfloat16 g_xl[(size_t)NMAX * 256];
__device__ __align__(16) __nv_bfloat16 g_w1h[256 * HDIM];
__device__ __align__(16) __nv_bfloat16 g_w1l[256 * HDIM];
// conv2/3 fp16 transposed weights
__device__ __align__(16) __half g_w2f[HDIM * HDIM];
__device__ __align__(16) __half g_w3f[HDIM * HDIM];

__device__ __forceinline__ int idx_at(const void* p, long long i, int is64) {
    if (is64) return (int)((const long long*)p)[i];
    return ((const int*)p)[i];
}

// ---------------- helpers ------------------------------------------------------
__device__ __forceinline__ uint32_t smem_u32(const void* p) {
    uint32_t a;
    asm("{ .reg .u64 t; cvta.to.shared.u64 t, %1; cvt.u32.u64 %0, t; }"
        : "=r"(a) : "l"(p));
    return a;
}
__device__ __forceinline__ void ldm_x4(uint32_t addr, uint32_t* r) {
    asm volatile("ldmatrix.sync.aligned.m8n8.x4.shared.b16 {%0,%1,%2,%3}, [%4];"
                 : "=r"(r[0]), "=r"(r[1]), "=r"(r[2]), "=r"(r[3]) : "r"(addr));
}
__device__ __forceinline__ void mma_bf16(float* c, const uint32_t* a,
                                         uint32_t b0, uint32_t b1) {
    asm volatile(
        "mma.sync.aligned.m16n8k16.row.col.f32.bf16.bf16.f32 "
        "{%0,%1,%2,%3}, {%4,%5,%6,%7}, {%8,%9}, {%0,%1,%2,%3};"
        : "+f"(c[0]), "+f"(c[1]), "+f"(c[2]), "+f"(c[3])
        : "r"(a[0]), "r"(a[1]), "r"(a[2]), "r"(a[3]), "r"(b0), "r"(b1));
}
__device__ __forceinline__ void mma_f16(float* c, const uint32_t* a,
                                        uint32_t b0, uint32_t b1) {
    asm volatile(
        "mma.sync.aligned.m16n8k16.row.col.f32.f16.f16.f32 "
        "{%0,%1,%2,%3}, {%4,%5,%6,%7}, {%8,%9}, {%0,%1,%2,%3};"
        : "+f"(c[0]), "+f"(c[1]), "+f"(c[2]), "+f"(c[3])
        : "r"(a[0]), "r"(a[1]), "r"(a[2]), "r"(a[3]), "r"(b0), "r"(b1));
}
__device__ __forceinline__ void split2(float x0, float x1,
                                       uint32_t& h01, uint32_t& l01) {
    __nv_bfloat16 h0 = __float2bfloat16_rn(x0);
    __nv_bfloat16 h1 = __float2bfloat16_rn(x1);
    __nv_bfloat16 l0 = __float2bfloat16_rn(x0 - __bfloat162float(h0));
    __nv_bfloat16 l1 = __float2bfloat16_rn(x1 - __bfloat162float(h1));
    h01 = (uint32_t)__bfloat16_as_ushort(h0) |
          ((uint32_t)__bfloat16_as_ushort(h1) << 16);
    l01 = (uint32_t)__bfloat16_as_ushort(l0) |
          ((uint32_t)__bfloat16_as_ushort(l1) << 16);
}
__device__ __forceinline__ void cpasync16(uint32_t dst, const void* src) {
    asm volatile("cp.async.cg.shared.global [%0], [%1], 16;"
                 :: "r"(dst), "l"(src));
}
__device__ __forceinline__ void cpasync_commit() {
    asm volatile("cp.async.commit_group;");
}
template <int N>
__device__ __forceinline__ void cpasync_wait() {
    asm volatile("cp.async.wait_group %0;" :: "n"(N));
}

// ---------------- init: zero deg + dtype probe (sticky flag) ------------------
__global__ void k_init(const unsigned* __restrict__ w, int nwords, int n) {
    int i = blockIdx.x * blockDim.x + threadIdx.x;
    if (i < n) g_deg[i] = 0;
    int odd = i * 2 + 1;
    if (odd < nwords && w[odd] != 0) g_not64 = 1;
}

__global__ void k_hist(const void* __restrict__ ei, int e) {
    int i = blockIdx.x * blockDim.x + threadIdx.x;
    if (i < e) {
        int is64 = (g_not64 == 0);
        int d = idx_at(ei, (long long)e + i, is64);
        atomicAdd(&g_deg[d], 1);
    }
}

__global__ void __launch_bounds__(SCAN_BLK)
k_scan1(int n) {
    __shared__ int wsum[32];
    const int t = threadIdx.x, lane = t & 31, wid = t >> 5;
    const int i = blockIdx.x * SCAN_BLK + t;
    int v = (i < n) ? g_deg[i] : 0;
    int s = v;
    #pragma unroll
    for (int o = 1; o < 32; o <<= 1) {
        int u = __shfl_up_sync(0xffffffffu, s, o);
        if (lane >= o) s += u;
    }
    if (lane == 31) wsum[wid] = s;
    __syncthreads();
    if (wid == 0) {
        int ws = wsum[lane];
        int sc = ws;
        #pragma unroll
        for (int o = 1; o < 32; o <<= 1) {
            int u = __shfl_up_sync(0xffffffffu, sc, o);
            if (lane >= o) sc += u;
        }
        wsum[lane] = sc - ws;
    }
    __syncthreads();
    s += wsum[wid];
    if (i < n) g_incl[i] = s;
    if (t == SCAN_BLK - 1) g_bsum[blockIdx.x] = s;
}

// scan2 folded in: every block redundantly scans the <=64 block sums.
__global__ void k_scan23(int nb, int n) {
    __shared__ int sboff[MAXNB];
    __shared__ int s_w0;
    const int t = threadIdx.x;
    const int lane = t & 31, w = t >> 5;
    int v = 0, s = 0;
    if (t < 64) {
        v = (t < nb) ? g_bsum[t] : 0;
        s = v;
        #pragma unroll
        for (int o = 1; o < 32; o <<= 1) {
            int u = __shfl_up_sync(0xffffffffu, s, o);
            if (lane >= o) s += u;
        }
        if (w == 0 && lane == 31) s_w0 = s;
    }
    __syncthreads();
    if (t < 64) {
        int incl = s + (w ? s_w0 : 0);
        sboff[t] = incl - v;
        if (blockIdx.x == 0 && t == nb - 1) g_rowptr[n] = incl;
    }
    __syncthreads();
    int i = blockIdx.x * blockDim.x + t;
    if (i < n) {
        int dv = g_deg[i];
        int excl = g_incl[i] - dv + sboff[i / SCAN_BLK];
        g_rowptr[i] = excl;
        g_cursor[i] = excl;
        g_dinv[i]   = rsqrtf((float)(dv + 1));
    }
}

// -------- prep: CSR fill + all conversions in one launch (block-partitioned) --
__global__ void k_prep(const void* __restrict__ ei, int e, int fblk,
                       const float* __restrict__ x,
                       const float* __restrict__ W1,
                       const float* __restrict__ W2,
                       const float* __restrict__ W3,
                       int n, int K1) {
    if (blockIdx.x < fblk) {
        int i = blockIdx.x * blockDim.x + threadIdx.x;
        if (i < e) {
            int is64 = (g_not64 == 0);
            int s = idx_at(ei, i, is64);
            int d = idx_at(ei, (long long)e + i, is64);
            int p = atomicAdd(&g_cursor[d], 1);
            g_col[p] = s;
        }
        return;
    }
    int idx = (blockIdx.x - fblk) * blockDim.x + threadIdx.x;
    const int tot_x = n * K1 / 8;
    if (idx < tot_x) {
        long long base = (long long)idx * 8;
        float4 v0 = *(const float4*)(x + base);
        float4 v1 = *(const float4*)(x + base + 4);
        uint32_t h01, l01, h23, l23, h45, l45, h67, l67;
        split2(v0.x, v0.y, h01, l01);
        split2(v0.z, v0.w, h23, l23);
        split2(v1.x, v1.y, h45, l45);
        split2(v1.z, v1.w, h67, l67);
        *(uint4*)(g_xh + base) = make_uint4(h01, h23, h45, h67);
        *(uint4*)(g_xl + base) = make_uint4(l01, l23, l45, l67);
        return;
    }
    int widx = idx - tot_x;
    const int n1 = K1 * 32;
    const int n2 = HDIM * 32;
    if (widx < n1) {
        int k = widx >> 5, n4 = widx & 31;
        float4 w = *(const float4*)(W1 + (size_t)k * HDIM + n4 * 4);
        float wv[4] = {w.x, w.y, w.z, w.w};
        #pragma unroll
        for (int j = 0; j < 4; j++) {
            __nv_bfloat16 h = __float2bfloat16_rn(wv[j]);
            __nv_bfloat16 l = __float2bfloat16_rn(wv[j] - __bfloat162float(h));
            g_w1h[(size_t)(n4 * 4 + j) * K1 + k] = h;
            g_w1l[(size_t)(n4 * 4 + j) * K1 + k] = l;
        }
    } else if (widx < n1 + 2 * n2) {
        int local = widx - n1;
        const float* W = (local < n2) ? W2 : W3;
        __half* dst = (local < n2) ? g_w2f : g_w3f;
        if (local >= n2) local -= n2;
        int k = local >> 5, n4 = local & 31;
        float4 w = *(const float4*)(W + (size_t)k * HDIM + n4 * 4);
        float wv[4] = {w.x, w.y, w.z, w.w};
        #pragma unroll
        for (int j = 0; j < 4; j++)
            dst[(size_t)(n4 * 4 + j) * HDIM + k] = __float2half_rn(wv[j]);
    }
}

// ---------------- conv1 GEMM: split-bf16, cp.async pipelined ------------------
#define RS2 40
#define AH_OFF 0
#define AL_OFF (128 * RS2 * 2)
#define BH_OFF (256 * RS2 * 2)
#define BL_OFF (320 * RS2 * 2)
#define STAGE_BYTES (384 * RS2 * 2)
#define GEMM_SMEM (2 * STAGE_BYTES)

__global__ void __launch_bounds__(256, 3)
k_gemm_bf16(int M, int K)
{
    extern __shared__ __align__(16) char smdyn[];
    const uint32_t smbase = smem_u32(smdyn);

    const __nv_bfloat16* Ah = g_xh;
    const __nv_bfloat16* Al = g_xl;
    const __nv_bfloat16* Wh = g_w1h;
    const __nv_bfloat16* Wl = g_w1l;

    const int tid  = threadIdx.x;
    const int wid  = tid >> 5;
    const int lane = tid & 31;
    const int wm   = wid >> 1;
    const int wn   = wid & 1;
    const int row0 = blockIdx.x * 128;
    const int n0   = blockIdx.y * 64;

    float acc[2][4][4];
    #pragma unroll
    for (int a = 0; a < 2; a++)
        #pragma unroll
        for (int b = 0; b < 4; b++)
            #pragma unroll
            for (int c = 0; c < 4; c++) acc[a][b][c] = 0.f;

    const int am_row  = wm * 32 + (lane & 15);
    const int am_colb = ((lane >> 4) & 1) * 16;
    const int bn_row  = wn * 32 + (lane & 7) + ((lane >> 4) & 1) * 8;
    const int bn_colb = (lane & 8) * 2;

    const int nchunk = K >> 5;

    #define PREFETCH(KC, SB)                                                     \
    {                                                                            \
        int k0p = (KC) * 32;                                                     \
        _Pragma("unroll")                                                        \
        for (int it = 0; it < 2; it++) {                                         \
            int cc = it * 256 + tid;                                             \
            int r = cc >> 2, q = cc & 3;                                         \
            int grow = row0 + r; if (grow > M - 1) grow = M - 1;                 \
            uint32_t doff = (uint32_t)((r * RS2 + q * 8) * 2);                   \
            cpasync16((SB) + AH_OFF + doff, Ah + (size_t)grow * K + k0p + q * 8);\
            cpasync16((SB) + AL_OFF + doff, Al + (size_t)grow * K + k0p + q * 8);\
        }                                                                        \
        {                                                                        \
            int r = tid >> 2, q = tid & 3;                                       \
            uint32_t doff = (uint32_t)((r * RS2 + q * 8) * 2);                   \
            cpasync16((SB) + BH_OFF + doff,                                      \
                      Wh + (size_t)(n0 + r) * K + k0p + q * 8);                  \
            cpasync16((SB) + BL_OFF + doff,                                      \
                      Wl + (size_t)(n0 + r) * K + k0p + q * 8);                  \
        }                                                                        \
        cpasync_commit();                                                        \
    }

    PREFETCH(0, smbase);

    for (int kc = 0; kc < nchunk; kc++) {
        const uint32_t sb = smbase + ((kc & 1) ? STAGE_BYTES : 0);
        if (kc + 1 < nchunk) {
            const uint32_t sbn = smbase + (((kc + 1) & 1) ? STAGE_BYTES : 0);
            PREFETCH(kc + 1, sbn);
            cpasync_wait<1>();
        } else {
            cpasync_wait<0>();
        }
        __syncthreads();

        #pragma unroll
        for (int s = 0; s < 2; s++) {
            uint32_t aH[2][4], aL[2][4], bHf[2][4], bLf[2][4];
            #pragma unroll
            for (int mt = 0; mt < 2; mt++) {
                uint32_t off = (uint32_t)((am_row + mt * 16) * (RS2 * 2)
                                          + s * 32 + am_colb);
                ldm_x4(sb + AH_OFF + off, aH[mt]);
                ldm_x4(sb + AL_OFF + off, aL[mt]);
            }
            #pragma unroll
            for (int np = 0; np < 2; np++) {
                uint32_t off = (uint32_t)((bn_row + np * 16) * (RS2 * 2)
                                          + s * 32 + bn_colb);
                ldm_x4(sb + BH_OFF + off, bHf[np]);
                ldm_x4(sb + BL_OFF + off, bLf[np]);
            }
            #pragma unroll
            for (int mt = 0; mt < 2; mt++)
                #pragma unroll
                for (int nt = 0; nt < 4; nt++) {
                    uint32_t b0 = bHf[nt >> 1][(nt & 1) * 2];
                    uint32_t b1 = bHf[nt >> 1][(nt & 1) * 2 + 1];
                    mma_bf16(acc[mt][nt], aH[mt], b0, b1);
                    mma_bf16(acc[mt][nt], aL[mt], b0, b1);
                    uint32_t c0 = bLf[nt >> 1][(nt & 1) * 2];
                    uint32_t c1 = bLf[nt >> 1][(nt & 1) * 2 + 1];
                    mma_bf16(acc[mt][nt], aH[mt], c0, c1);
                }
        }
        __syncthreads();
    }
    #undef PREFETCH

    const int rbase = row0 + wm * 32 + (lane >> 2);
    const int cbase = n0 + wn * 32 + (lane & 3) * 2;
    #pragma unroll
    for (int mt = 0; mt < 2; mt++) {
        int r0 = rbase + mt * 16;
        int r1 = r0 + 8;
        float d0 = (r0 < M) ? g_dinv[r0] : 0.f;
        float d1 = (r1 < M) ? g_dinv[r1] : 0.f;
        #pragma unroll
        for (int nt = 0; nt < 4; nt++) {
            int c = cbase + nt * 8;
            if (r0 < M) {
                __half2 h = __floats2half2_rn(acc[mt][nt][0] * d0,
                                              acc[mt][nt][1] * d0);
                *(__half2*)(g_yh + (size_t)r0 * HDIM + c) = h;
            }
            if (r1 < M) {
                __half2 h = __floats2half2_rn(acc[mt][nt][2] * d1,
                                              acc[mt][nt][3] * d1);
                *(__half2*)(g_yh + (size_t)r1 * HDIM + c) = h;
            }
        }
    }
}

// ------ fused aggr + GEMM (conv2/3): gather -> smem h tile -> HMMA -> dst -----
// CONV==2: src g_yh,  W g_w2f, dst g_yh2.  CONV==3: src g_yh2, W g_w3f, dst g_yh.
#define RS3 136
#define FUSED_SMEM (2 * 128 * RS3 * 2)   // A tile + W tile = 69632 B

template <int CONV>
__global__ void __launch_bounds__(256, 2)
k_fused(const float* __restrict__ bias,
        const float* __restrict__ bng, const float* __restrict__ bnb,
        const float* __restrict__ bnm, const float* __restrict__ bnv,
        int n)
{
    extern __shared__ __align__(16) char smdyn[];
    const uint32_t as_base = smem_u32(smdyn);
    const uint32_t ws_base = as_base + 128 * RS3 * 2;
    __half* As = (__half*)smdyn;

    const __half* src = (CONV == 2) ? g_yh : g_yh2;
    const __half* Wf  = (CONV == 2) ? g_w2f : g_w3f;
    __half* dst       = (CONV == 2) ? g_yh2 : g_yh;

    const int tid  = threadIdx.x;
    const int wid  = tid >> 5;
    const int lane = tid & 31;
    const int row0 = blockIdx.x * 128;

    // ---- W tile load: 128x128 fp16 = 2048 16B chunks, 8 per thread ----
    #pragma unroll
    for (int it = 0; it < 8; it++) {
        int id = it * 256 + tid;
        int r = id >> 4, q = id & 15;
        uint32_t doff = (uint32_t)((r * RS3 + q * 8) * 2);
        cpasync16(ws_base + doff, Wf + (size_t)r * HDIM + q * 8);
    }
    cpasync_commit();

    // ---- gather phase: warp per row, 16 rows per warp ----
    const int c = lane * 4;
    for (int lr = wid; lr < 128; lr += 8) {
        int row = row0 + lr;
        float4 r4 = make_float4(0.f, 0.f, 0.f, 0.f);
        if (row < n) {
            float4 acc;
            {
                uint2 v = *(const uint2*)(src + (size_t)row * HDIM + c);
                float2 f0 = __half22float2(*(__half2*)&v.x);
                float2 f1 = __half22float2(*(__half2*)&v.y);
                acc.x = f0.x; acc.y = f0.y; acc.z = f1.x; acc.w = f1.y;
            }
            int e   = g_rowptr[row];
            int end = g_rowptr[row + 1];
            for (; e + 8 <= end; e += 8) {
                uint2 u[8];
                #pragma unroll
                for (int j = 0; j < 8; j++) {
                    int cc = g_col[e + j];
                    u[j] = *(const uint2*)(src + (size_t)cc * HDIM + c);
                }
                #pragma unroll
                for (int j = 0; j < 8; j++) {
                    float2 a = __half22float2(*(__half2*)&u[j].x);
                    float2 b = __half22float2(*(__half2*)&u[j].y);
                    acc.x += a.x; acc.y += a.y; acc.z += b.x; acc.w += b.y;
                }
            }
            for (; e < end; e++) {
                int cc = g_col[e];
                uint2 u = *(const uint2*)(src + (size_t)cc * HDIM + c);
                float2 a = __half22float2(*(__half2*)&u.x);
                float2 b = __half22float2(*(__half2*)&u.y);
                acc.x += a.x; acc.y += a.y; acc.z += b.x; acc.w += b.y;
            }
            const float dvw = g_dinv[row];
            r4.x = acc.x * dvw + bias[c + 0];
            r4.y = acc.y * dvw + bias[c + 1];
            r4.z = acc.z * dvw + bias[c + 2];
            r4.w = acc.w * dvw + bias[c + 3];
            // BN + ReLU (always on for conv2/3 inputs h1/h2)
            float i0 = rsqrtf(bnv[c + 0] + BN_EPS_F);
            float i1 = rsqrtf(bnv[c + 1] + BN_EPS_F);
            float i2 = rsqrtf(bnv[c + 2] + BN_EPS_F);
            float i3 = rsqrtf(bnv[c + 3] + BN_EPS_F);
            r4.x = fmaxf((r4.x - bnm[c + 0]) * i0 * bng[c + 0] + bnb[c + 0], 0.f);
            r4.y = fmaxf((r4.y - bnm[c + 1]) * i1 * bng[c + 1] + bnb[c + 1], 0.f);
            r4.z = fmaxf((r4.z - bnm[c + 2]) * i2 * bng[c + 2] + bnb[c + 2], 0.f);
            r4.w = fmaxf((r4.w - bnm[c + 3]) * i3 * bng[c + 3] + bnb[c + 3], 0.f);
        }
        __half2 h0 = __floats2half2_rn(r4.x, r4.y);
        __half2 h1 = __floats2half2_rn(r4.z, r4.w);
        uint2 o;
        o.x = *(uint32_t*)&h0;
        o.y = *(uint32_t*)&h1;
        *(uint2*)(As + (size_t)lr * RS3 + c) = o;
    }
    cpasync_wait<0>();
    __syncthreads();

    // ---- MMA phase (R7 geometry: 8 warps = 2m(64) x 4n(32)) ----
    const int wm = wid >> 2;
    const int wn = wid & 3;
    float acc[4][4][4];
    #pragma unroll
    for (int a = 0; a < 4; a++)
        #pragma unroll
        for (int b = 0; b < 4; b++)
            #pragma unroll
            for (int d = 0; d < 4; d++) acc[a][b][d] = 0.f;

    const int am_row  = wm * 64 + (lane & 15);
    const int am_colb = ((lane >> 4) & 1) * 16;
    const int bn_row  = wn * 32 + (lane & 7) + ((lane >> 4) & 1) * 8;
    const int bn_colb = (lane & 8) * 2;

    #pragma unroll
    for (int s = 0; s < 8; s++) {
        uint32_t aF[4][4], bF[2][4];
        #pragma unroll
        for (int mt = 0; mt < 4; mt++) {
            uint32_t off = (uint32_t)((am_row + mt * 16) * (RS3 * 2)
                                      + s * 32 + am_colb);
            ldm_x4(as_base + off, aF[mt]);
        }
        #pragma unroll
        for (int np = 0; np < 2; np++) {
            uint32_t off = (uint32_t)((bn_row + np * 16) * (RS3 * 2)
                                      + s * 32 + bn_colb);
            ldm_x4(ws_base + off, bF[np]);
        }
        #pragma unroll
        for (int mt = 0; mt < 4; mt++)
            #pragma unroll
            for (int nt = 0; nt < 4; nt++) {
                uint32_t b0 = bF[nt >> 1][(nt & 1) * 2];
                uint32_t b1 = bF[nt >> 1][(nt & 1) * 2 + 1];
                mma_f16(acc[mt][nt], aF[mt], b0, b1);
            }
    }

    // ---- epilogue: y*dinv -> fp16 dst ----
    const int rbase = row0 + wm * 64 + (lane >> 2);
    const int cbase = wn * 32 + (lane & 3) * 2;
    #pragma unroll
    for (int mt = 0; mt < 4; mt++) {
        int r0 = rbase + mt * 16;
        int r1 = r0 + 8;
        float d0 = (r0 < n) ? g_dinv[r0] : 0.f;
        float d1 = (r1 < n) ? g_dinv[r1] : 0.f;
        #pragma unroll
        for (int nt = 0; nt < 4; nt++) {
            int cc = cbase + nt * 8;
            if (r0 < n) {
                __half2 h = __floats2half2_rn(acc[mt][nt][0] * d0,
                                              acc[mt][nt][1] * d0);
                *(__half2*)(dst + (size_t)r0 * HDIM + cc) = h;
            }
            if (r1 < n) {
                __half2 h = __floats2half2_rn(acc[mt][nt][2] * d1,
                                              acc[mt][nt][3] * d1);
                *(__half2*)(dst + (size_t)r1 * HDIM + cc) = h;
            }
        }
    }
}

// -------- aggr3: gathers fp16 g_yh (8-way MLP), bias only, writes fp16 g_af ---
__global__ void __launch_bounds__(256)
k_aggr3(const float* __restrict__ bias, int n)
{
    int w = (blockIdx.x * blockDim.x + threadIdx.x) >> 5;
    if (w >= n) return;
    const int lane = threadIdx.x & 31;
    const int c = lane * 4;

    float4 acc;
    {
        uint2 v = *(const uint2*)(g_yh + (size_t)w * HDIM + c);
        float2 f0 = __half22float2(*(__half2*)&v.x);
        float2 f1 = __half22float2(*(__half2*)&v.y);
        acc.x = f0.x; acc.y = f0.y; acc.z = f1.x; acc.w = f1.y;
    }

    int e   = g_rowptr[w];
    int end = g_rowptr[w + 1];
    for (; e + 8 <= end; e += 8) {
        uint2 u[8];
        #pragma unroll
        for (int j = 0; j < 8; j++) {
            int cc = g_col[e + j];
            u[j] = *(const uint2*)(g_yh + (size_t)cc * HDIM + c);
        }
        #pragma unroll
        for (int j = 0; j < 8; j++) {
            float2 a = __half22float2(*(__half2*)&u[j].x);
            float2 b = __half22float2(*(__half2*)&u[j].y);
            acc.x += a.x; acc.y += a.y; acc.z += b.x; acc.w += b.y;
        }
    }
    for (; e < end; e++) {
        int cc = g_col[e];
        uint2 u = *(const uint2*)(g_yh + (size_t)cc * HDIM + c);
        float2 a = __half22float2(*(__half2*)&u.x);
        float2 b = __half22float2(*(__half2*)&u.y);
        acc.x += a.x; acc.y += a.y; acc.z += b.x; acc.w += b.y;
    }

    const float dvw = g_dinv[w];
    __half2 h0 = __floats2half2_rn(acc.x * dvw + bias[c + 0],
                                   acc.y * dvw + bias[c + 1]);
    __half2 h1 = __floats2half2_rn(acc.z * dvw + bias[c + 2],
                                   acc.w * dvw + bias[c + 3]);
    uint2 o;
    o.x = *(uint32_t*)&h0;
    o.y = *(uint32_t*)&h1;
    *(uint2*)(g_af + (size_t)w * HDIM + c) = o;
}

// ---------------- fused pool + classifier: block g handles graph g ------------
__device__ __forceinline__ int lower_bound_idx(const void* b, int n, int key, int is64) {
    int lo = 0, hi = n;
    while (lo < hi) {
        int mid = (lo + hi) >> 1;
        int v = idx_at(b, mid, is64);
        if (v < key) lo = mid + 1; else hi = mid;
    }
    return lo;
}

__global__ void __launch_bounds__(256)
k_poolcls(const void* __restrict__ batch, int n,
          const float* __restrict__ Wc1, const float* __restrict__ bc1,
          const float* __restrict__ Wc2, const float* __restrict__ bc2,
          float* __restrict__ out)
{
    __shared__ float red[256];
    __shared__ float pooled[128];
    __shared__ float z[64];
    const int g = blockIdx.x;
    const int t = threadIdx.x;
    const int col  = t & 127;
    const int half = t >> 7;
    const int is64 = (g_not64 == 0);

    int start = lower_bound_idx(batch, n, g, is64);
    int end   = lower_bound_idx(batch, n, g + 1, is64);

    float a0 = 0.f, a1 = 0.f, a2 = 0.f, a3 = 0.f;
    int r = start + half;
    for (; r + 6 < end; r += 8) {
        a0 += __half2float(g_af[(size_t)r * HDIM + col]);
        a1 += __half2float(g_af[(size_t)(r + 2) * HDIM + col]);
        a2 += __half2float(g_af[(size_t)(r + 4) * HDIM + col]);
        a3 += __half2float(g_af[(size_t)(r + 6) * HDIM + col]);
    }
    for (; r < end; r += 2) a0 += __half2float(g_af[(size_t)r * HDIM + col]);
    red[t] = (a0 + a1) + (a2 + a3);
    __syncthreads();
    if (half == 0) {
        float cnt = (float)(end - start);
        pooled[col] = (red[t] + red[t + 128]) / fmaxf(cnt, 1.f);
    }
    __syncthreads();

    if (t < 64) {
        float s = bc1[t];
        #pragma unroll 8
        for (int k = 0; k < HDIM; k++)
            s = fmaf(pooled[k], Wc1[k * 64 + t], s);
        z[t] = fmaxf(s, 0.f);
    }
    __syncthreads();

    if (t < 16) {
        float s = bc2[t];
        #pragma unroll
        for (int k = 0; k < 64; k++)
            s = fmaf(z[k], Wc2[k * 16 + t], s);
        out[g * 16 + t] = s;
    }
}

// ---------------- launch -------------------------------------------------------
extern "C" void kernel_launch(void* const* d_in, const int* in_sizes, int n_in,
                              void* d_out, int out_size)
{
    const float* x     = (const float*)d_in[0];
    const void*  ei    = d_in[1];
    const void*  batch = d_in[2];
    const float* W1  = (const float*)d_in[3];
    const float* b1  = (const float*)d_in[4];
    const float* W2  = (const float*)d_in[5];
    const float* b2  = (const float*)d_in[6];
    const float* W3  = (const float*)d_in[7];
    const float* b3  = (const float*)d_in[8];
    const float* bn1g = (const float*)d_in[9];
    const float* bn1b = (const float*)d_in[10];
    const float* bn1m = (const float*)d_in[11];
    const float* bn1v = (const float*)d_in[12];
    const float* bn2g = (const float*)d_in[13];
    const float* bn2b = (const float*)d_in[14];
    const float* bn2m = (const float*)d_in[15];
    const float* bn2v = (const float*)d_in[16];
    const float* Wc1 = (const float*)d_in[17];
    const float* bc1 = (const float*)d_in[18];
    const float* Wc2 = (const float*)d_in[19];
    const float* bc2 = (const float*)d_in[20];

    const int n = in_sizes[2];
    const int e = in_sizes[1] / 2;
    const int K1 = in_sizes[0] / n;     // 256
    const int nb = (n + SCAN_BLK - 1) / SCAN_BLK;

    cudaFuncSetAttribute(k_gemm_bf16,
                         cudaFuncAttributeMaxDynamicSharedMemorySize, GEMM_SMEM);
    cudaFuncSetAttribute(k_fused<2>,
                         cudaFuncAttributeMaxDynamicSharedMemorySize, FUSED_SMEM);
    cudaFuncSetAttribute(k_fused<3>,
                         cudaFuncAttributeMaxDynamicSharedMemorySize, FUSED_SMEM);

    const int gblk = (n + 127) / 128;
    const int ablk = ((n * 32) + 255) / 256;
    dim3 ggrid(gblk, 2);

    int nwords = in_sizes[1];
    if (nwords > 16384) nwords = 16384;
    int init_items = n > (nwords + 1) / 2 ? n : (nwords + 1) / 2;

    const int fblk = (e + 255) / 256;
    const int tot_s = n * K1 / 8 + K1 * 32 + 2 * HDIM * 32;
    const int sblk = (tot_s + 255) / 256;

    // 10 launches total
    k_init<<<(init_items + 255) / 256, 256>>>((const unsigned*)ei, nwords, n); // 0
    k_hist<<<(e + 255) / 256, 256>>>(ei, e);                                   // 1
    k_scan1<<<nb, SCAN_BLK>>>(n);                                              // 2
    k_scan23<<<(n + 255) / 256, 256>>>(nb, n);                                 // 3
    k_prep<<<fblk + sblk, 256>>>(ei, e, fblk, x, W1, W2, W3, n, K1);           // 4
    // conv1 gemm
    k_gemm_bf16<<<ggrid, 256, GEMM_SMEM>>>(n, K1);                             // 5
    // conv2 = aggr1(BN1) + gemm2  (g_yh -> g_yh2)
    k_fused<2><<<gblk, 256, FUSED_SMEM>>>(b1, bn1g, bn1b, bn1m, bn1v, n);      // 6
    // conv3 = aggr2(BN2) + gemm3  (g_yh2 -> g_yh)
    k_fused<3><<<gblk, 256, FUSED_SMEM>>>(b2, bn2g, bn2b, bn2m, bn2v, n);      // 7
    // aggr3 (bias only) -> g_af
    k_aggr3<<<ablk, 256>>>(b3, n);                                             // 8
    // fused pool + classifier
    k_poolcls<<<NG, 256>>>(batch, n, Wc1, bc1, Wc2, bc2, (float*)d_out);       // 9
}

// round 17
// speedup vs baseline: 1.2782x; 1.2782x over previous
#include <cuda_runtime.h>
#include <cuda_bf16.h>
#include <cuda_fp16.h>
#include <cstdint>
#include <cstddef>

#define NMAX 50000
#define EMAX 800000
#define HDIM 128
#define NG 64
#define BN_EPS_F 1e-5f
#define SCAN_BLK 1024
#define MAXNB 64

// ---------------- scratch (static device globals; no runtime alloc) ----------
__device__ int   g_not64 = 0;          // sticky: 1 if int inputs are int32
__device__ int   g_deg[NMAX];
__device__ int   g_incl[NMAX];
__device__ int   g_bsum[MAXNB];
__device__ int   g_rowptr[NMAX + 1];
__device__ int   g_cursor[NMAX];
__device__ int   g_col[EMAX];
__device__ float g_dinv[NMAX];
__device__ __align__(16) __half g_yh[(size_t)NMAX * HDIM];   // y*dinv[row], fp16
__device__ __align__(16) __half g_af[(size_t)NMAX * HDIM];   // h (fp16)
// conv1 split-bf16 planes
__device__ __align__(16) __nv_bfloat16 g_xh[(size_t)NMAX * 256];
__device__ __align__(16) __nv_bfloat16 g_xl[(size_t)NMAX * 256];
__device__ __align__(16) __nv_bfloat16 g_w1h[256 * HDIM];
__device__ __align__(16) __nv_bfloat16 g_w1l[256 * HDIM];
// conv2/3 fp16 transposed weights
__device__ __align__(16) __half g_w2f[HDIM * HDIM];
__device__ __align__(16) __half g_w3f[HDIM * HDIM];

__device__ __forceinline__ int idx_at(const void* p, long long i, int is64) {
    if (is64) return (int)((const long long*)p)[i];
    return ((const int*)p)[i];
}

// ---------------- helpers ------------------------------------------------------
__device__ __forceinline__ uint32_t smem_u32(const void* p) {
    uint32_t a;
    asm("{ .reg .u64 t; cvta.to.shared.u64 t, %1; cvt.u32.u64 %0, t; }"
        : "=r"(a) : "l"(p));
    return a;
}
__device__ __forceinline__ void ldm_x4(uint32_t addr, uint32_t* r) {
    asm volatile("ldmatrix.sync.aligned.m8n8.x4.shared.b16 {%0,%1,%2,%3}, [%4];"
                 : "=r"(r[0]), "=r"(r[1]), "=r"(r[2]), "=r"(r[3]) : "r"(addr));
}
__device__ __forceinline__ void mma_bf16(float* c, const uint32_t* a,
                                         uint32_t b0, uint32_t b1) {
    asm volatile(
        "mma.sync.aligned.m16n8k16.row.col.f32.bf16.bf16.f32 "
        "{%0,%1,%2,%3}, {%4,%5,%6,%7}, {%8,%9}, {%0,%1,%2,%3};"
        : "+f"(c[0]), "+f"(c[1]), "+f"(c[2]), "+f"(c[3])
        : "r"(a[0]), "r"(a[1]), "r"(a[2]), "r"(a[3]), "r"(b0), "r"(b1));
}
__device__ __forceinline__ void mma_f16(float* c, const uint32_t* a,
                                        uint32_t b0, uint32_t b1) {
    asm volatile(
        "mma.sync.aligned.m16n8k16.row.col.f32.f16.f16.f32 "
        "{%0,%1,%2,%3}, {%4,%5,%6,%7}, {%8,%9}, {%0,%1,%2,%3};"
        : "+f"(c[0]), "+f"(c[1]), "+f"(c[2]), "+f"(c[3])
        : "r"(a[0]), "r"(a[1]), "r"(a[2]), "r"(a[3]), "r"(b0), "r"(b1));
}
__device__ __forceinline__ void split2(float x0, float x1,
                                       uint32_t& h01, uint32_t& l01) {
    __nv_bfloat16 h0 = __float2bfloat16_rn(x0);
    __nv_bfloat16 h1 = __float2bfloat16_rn(x1);
    __nv_bfloat16 l0 = __float2bfloat16_rn(x0 - __bfloat162float(h0));
    __nv_bfloat16 l1 = __float2bfloat16_rn(x1 - __bfloat162float(h1));
    h01 = (uint32_t)__bfloat16_as_ushort(h0) |
          ((uint32_t)__bfloat16_as_ushort(h1) << 16);
    l01 = (uint32_t)__bfloat16_as_ushort(l0) |
          ((uint32_t)__bfloat16_as_ushort(l1) << 16);
}
__device__ __forceinline__ void cpasync16(uint32_t dst, const void* src) {
    asm volatile("cp.async.cg.shared.global [%0], [%1], 16;"
                 :: "r"(dst), "l"(src));
}
__device__ __forceinline__ void cpasync_commit() {
    asm volatile("cp.async.commit_group;");
}
template <int N>
__device__ __forceinline__ void cpasync_wait() {
    asm volatile("cp.async.wait_group %0;" :: "n"(N));
}

// ---------------- init: zero deg + dtype probe (sticky flag) ------------------
__global__ void k_init(const unsigned* __restrict__ w, int nwords, int n) {
    int i = blockIdx.x * blockDim.x + threadIdx.x;
    if (i < n) g_deg[i] = 0;
    int odd = i * 2 + 1;
    if (odd < nwords && w[odd] != 0) g_not64 = 1;
}

__global__ void k_hist(const void* __restrict__ ei, int e) {
    int i = blockIdx.x * blockDim.x + threadIdx.x;
    if (i < e) {
        int is64 = (g_not64 == 0);
        int d = idx_at(ei, (long long)e + i, is64);
        atomicAdd(&g_deg[d], 1);
    }
}

__global__ void __launch_bounds__(SCAN_BLK)
k_scan1(int n) {
    __shared__ int wsum[32];
    const int t = threadIdx.x, lane = t & 31, wid = t >> 5;
    const int i = blockIdx.x * SCAN_BLK + t;
    int v = (i < n) ? g_deg[i] : 0;
    int s = v;
    #pragma unroll
    for (int o = 1; o < 32; o <<= 1) {
        int u = __shfl_up_sync(0xffffffffu, s, o);
        if (lane >= o) s += u;
    }
    if (lane == 31) wsum[wid] = s;
    __syncthreads();
    if (wid == 0) {
        int ws = wsum[lane];
        int sc = ws;
        #pragma unroll
        for (int o = 1; o < 32; o <<= 1) {
            int u = __shfl_up_sync(0xffffffffu, sc, o);
            if (lane >= o) sc += u;
        }
        wsum[lane] = sc - ws;
    }
    __syncthreads();
    s += wsum[wid];
    if (i < n) g_incl[i] = s;
    if (t == SCAN_BLK - 1) g_bsum[blockIdx.x] = s;
}

// scan2 folded in: every block redundantly scans the <=64 block sums.
__global__ void k_scan23(int nb, int n) {
    __shared__ int sboff[MAXNB];
    __shared__ int s_w0;
    const int t = threadIdx.x;
    const int lane = t & 31, w = t >> 5;
    int v = 0, s = 0;
    if (t < 64) {
        v = (t < nb) ? g_bsum[t] : 0;
        s = v;
        #pragma unroll
        for (int o = 1; o < 32; o <<= 1) {
            int u = __shfl_up_sync(0xffffffffu, s, o);
            if (lane >= o) s += u;
        }
        if (w == 0 && lane == 31) s_w0 = s;
    }
    __syncthreads();
    if (t < 64) {
        int incl = s + (w ? s_w0 : 0);
        sboff[t] = incl - v;
        if (blockIdx.x == 0 && t == nb - 1) g_rowptr[n] = incl;
    }
    __syncthreads();
    int i = blockIdx.x * blockDim.x + t;
    if (i < n) {
        int dv = g_deg[i];
        int excl = g_incl[i] - dv + sboff[i / SCAN_BLK];
        g_rowptr[i] = excl;
        g_cursor[i] = excl;
        g_dinv[i]   = rsqrtf((float)(dv + 1));
    }
}

// -------- prep: CSR fill + all conversions in one launch (block-partitioned) --
__global__ void k_prep(const void* __restrict__ ei, int e, int fblk,
                       const float* __restrict__ x,
                       const float* __restrict__ W1,
                       const float* __restrict__ W2,
                       const float* __restrict__ W3,
                       int n, int K1) {
    if (blockIdx.x < fblk) {
        int i = blockIdx.x * blockDim.x + threadIdx.x;
        if (i < e) {
            int is64 = (g_not64 == 0);
            int s = idx_at(ei, i, is64);
            int d = idx_at(ei, (long long)e + i, is64);
            int p = atomicAdd(&g_cursor[d], 1);
            g_col[p] = s;
        }
        return;
    }
    int idx = (blockIdx.x - fblk) * blockDim.x + threadIdx.x;
    const int tot_x = n * K1 / 8;
    if (idx < tot_x) {
        long long base = (long long)idx * 8;
        float4 v0 = *(const float4*)(x + base);
        float4 v1 = *(const float4*)(x + base + 4);
        uint32_t h01, l01, h23, l23, h45, l45, h67, l67;
        split2(v0.x, v0.y, h01, l01);
        split2(v0.z, v0.w, h23, l23);
        split2(v1.x, v1.y, h45, l45);
        split2(v1.z, v1.w, h67, l67);
        *(uint4*)(g_xh + base) = make_uint4(h01, h23, h45, h67);
        *(uint4*)(g_xl + base) = make_uint4(l01, l23, l45, l67);
        return;
    }
    int widx = idx - tot_x;
    const int n1 = K1 * 32;
    const int n2 = HDIM * 32;
    if (widx < n1) {
        int k = widx >> 5, n4 = widx & 31;
        float4 w = *(const float4*)(W1 + (size_t)k * HDIM + n4 * 4);
        float wv[4] = {w.x, w.y, w.z, w.w};
        #pragma unroll
        for (int j = 0; j < 4; j++) {
            __nv_bfloat16 h = __float2bfloat16_rn(wv[j]);
            __nv_bfloat16 l = __float2bfloat16_rn(wv[j] - __bfloat162float(h));
            g_w1h[(size_t)(n4 * 4 + j) * K1 + k] = h;
            g_w1l[(size_t)(n4 * 4 + j) * K1 + k] = l;
        }
    } else if (widx < n1 + 2 * n2) {
        int local = widx - n1;
        const float* W = (local < n2) ? W2 : W3;
        __half* dst = (local < n2) ? g_w2f : g_w3f;
        if (local >= n2) local -= n2;
        int k = local >> 5, n4 = local & 31;
        float4 w = *(const float4*)(W + (size_t)k * HDIM + n4 * 4);
        float wv[4] = {w.x, w.y, w.z, w.w};
        #pragma unroll
        for (int j = 0; j < 4; j++)
            dst[(size_t)(n4 * 4 + j) * HDIM + k] = __float2half_rn(wv[j]);
    }
}

// ---------------- conv1 GEMM: split-bf16, cp.async pipelined ------------------
#define RS2 40
#define AH_OFF 0
#define AL_OFF (128 * RS2 * 2)
#define BH_OFF (256 * RS2 * 2)
#define BL_OFF (320 * RS2 * 2)
#define STAGE_BYTES (384 * RS2 * 2)
#define GEMM_SMEM (2 * STAGE_BYTES)

__global__ void __launch_bounds__(256, 3)
k_gemm_bf16(int M, int K)
{
    extern __shared__ __align__(16) char smdyn[];
    const uint32_t smbase = smem_u32(smdyn);

    const __nv_bfloat16* Ah = g_xh;
    const __nv_bfloat16* Al = g_xl;
    const __nv_bfloat16* Wh = g_w1h;
    const __nv_bfloat16* Wl = g_w1l;

    const int tid  = threadIdx.x;
    const int wid  = tid >> 5;
    const int lane = tid & 31;
    const int wm   = wid >> 1;
    const int wn   = wid & 1;
    const int row0 = blockIdx.x * 128;
    const int n0   = blockIdx.y * 64;

    float acc[2][4][4];
    #pragma unroll
    for (int a = 0; a < 2; a++)
        #pragma unroll
        for (int b = 0; b < 4; b++)
            #pragma unroll
            for (int c = 0; c < 4; c++) acc[a][b][c] = 0.f;

    const int am_row  = wm * 32 + (lane & 15);
    const int am_colb = ((lane >> 4) & 1) * 16;
    const int bn_row  = wn * 32 + (lane & 7) + ((lane >> 4) & 1) * 8;
    const int bn_colb = (lane & 8) * 2;

    const int nchunk = K >> 5;

    #define PREFETCH(KC, SB)                                                     \
    {                                                                            \
        int k0p = (KC) * 32;                                                     \
        _Pragma("unroll")                                                        \
        for (int it = 0; it < 2; it++) {                                         \
            int cc = it * 256 + tid;                                             \
            int r = cc >> 2, q = cc & 3;                                         \
            int grow = row0 + r; if (grow > M - 1) grow = M - 1;                 \
            uint32_t doff = (uint32_t)((r * RS2 + q * 8) * 2);                   \
            cpasync16((SB) + AH_OFF + doff, Ah + (size_t)grow * K + k0p + q * 8);\
            cpasync16((SB) + AL_OFF + doff, Al + (size_t)grow * K + k0p + q * 8);\
        }                                                                        \
        {                                                                        \
            int r = tid >> 2, q = tid & 3;                                       \
            uint32_t doff = (uint32_t)((r * RS2 + q * 8) * 2);                   \
            cpasync16((SB) + BH_OFF + doff,                                      \
                      Wh + (size_t)(n0 + r) * K + k0p + q * 8);                  \
            cpasync16((SB) + BL_OFF + doff,                                      \
                      Wl + (size_t)(n0 + r) * K + k0p + q * 8);                  \
        }                                                                        \
        cpasync_commit();                                                        \
    }

    PREFETCH(0, smbase);

    for (int kc = 0; kc < nchunk; kc++) {
        const uint32_t sb = smbase + ((kc & 1) ? STAGE_BYTES : 0);
        if (kc + 1 < nchunk) {
            const uint32_t sbn = smbase + (((kc + 1) & 1) ? STAGE_BYTES : 0);
            PREFETCH(kc + 1, sbn);
            cpasync_wait<1>();
        } else {
            cpasync_wait<0>();
        }
        __syncthreads();

        #pragma unroll
        for (int s = 0; s < 2; s++) {
            uint32_t aH[2][4], aL[2][4], bHf[2][4], bLf[2][4];
            #pragma unroll
            for (int mt = 0; mt < 2; mt++) {
                uint32_t off = (uint32_t)((am_row + mt * 16) * (RS2 * 2)
                                          + s * 32 + am_colb);
                ldm_x4(sb + AH_OFF + off, aH[mt]);
                ldm_x4(sb + AL_OFF + off, aL[mt]);
            }
            #pragma unroll
            for (int np = 0; np < 2; np++) {
                uint32_t off = (uint32_t)((bn_row + np * 16) * (RS2 * 2)
                                          + s * 32 + bn_colb);
                ldm_x4(sb + BH_OFF + off, bHf[np]);
                ldm_x4(sb + BL_OFF + off, bLf[np]);
            }
            #pragma unroll
            for (int mt = 0; mt < 2; mt++)
                #pragma unroll
                for (int nt = 0; nt < 4; nt++) {
                    uint32_t b0 = bHf[nt >> 1][(nt & 1) * 2];
                    uint32_t b1 = bHf[nt >> 1][(nt & 1) * 2 + 1];
                    mma_bf16(acc[mt][nt], aH[mt], b0, b1);
                    mma_bf16(acc[mt][nt], aL[mt], b0, b1);
                    uint32_t c0 = bLf[nt >> 1][(nt & 1) * 2];
                    uint32_t c1 = bLf[nt >> 1][(nt & 1) * 2 + 1];
                    mma_bf16(acc[mt][nt], aH[mt], c0, c1);
                }
        }
        __syncthreads();
    }
    #undef PREFETCH

    const int rbase = row0 + wm * 32 + (lane >> 2);
    const int cbase = n0 + wn * 32 + (lane & 3) * 2;
    #pragma unroll
    for (int mt = 0; mt < 2; mt++) {
        int r0 = rbase + mt * 16;
        int r1 = r0 + 8;
        float d0 = (r0 < M) ? g_dinv[r0] : 0.f;
        float d1 = (r1 < M) ? g_dinv[r1] : 0.f;
        #pragma unroll
        for (int nt = 0; nt < 4; nt++) {
            int c = cbase + nt * 8;
            if (r0 < M) {
                __half2 h = __floats2half2_rn(acc[mt][nt][0] * d0,
                                              acc[mt][nt][1] * d0);
                *(__half2*)(g_yh + (size_t)r0 * HDIM + c) = h;
            }
            if (r1 < M) {
                __half2 h = __floats2half2_rn(acc[mt][nt][2] * d1,
                                              acc[mt][nt][3] * d1);
                *(__half2*)(g_yh + (size_t)r1 * HDIM + c) = h;
            }
        }
    }
}

// ---------------- conv2/3 GEMM: fp16 single-plane, cp.async pipelined ---------
#define AF_OFF 0
#define BF_OFF (128 * RS2 * 2)
#define STAGE_F (192 * RS2 * 2)
#define GEMM_SMEM_F (2 * STAGE_F)

template <int CONV>
__global__ void __launch_bounds__(256, 4)
k_gemm_f16(int M)
{
    extern __shared__ __align__(16) char smdyn[];
    const uint32_t smbase = smem_u32(smdyn);
    const int K = HDIM;

    const __half* Af = g_af;
    const __half* Wf = (CONV == 2) ? g_w2f : g_w3f;

    const int tid  = threadIdx.x;
    const int wid  = tid >> 5;
    const int lane = tid & 31;
    const int wm   = wid >> 1;
    const int wn   = wid & 1;
    const int row0 = blockIdx.x * 128;
    const int n0   = blockIdx.y * 64;

    float acc[2][4][4];
    #pragma unroll
    for (int a = 0; a < 2; a++)
        #pragma unroll
        for (int b = 0; b < 4; b++)
            #pragma unroll
            for (int c = 0; c < 4; c++) acc[a][b][c] = 0.f;

    const int am_row  = wm * 32 + (lane & 15);
    const int am_colb = ((lane >> 4) & 1) * 16;
    const int bn_row  = wn * 32 + (lane & 7) + ((lane >> 4) & 1) * 8;
    const int bn_colb = (lane & 8) * 2;

    const int nchunk = K >> 5;

    #define PREFETCHF(KC, SB)                                                    \
    {                                                                            \
        int k0p = (KC) * 32;                                                     \
        _Pragma("unroll")                                                        \
        for (int it = 0; it < 2; it++) {                                         \
            int cc = it * 256 + tid;                                             \
            int r = cc >> 2, q = cc & 3;                                         \
            int grow = row0 + r; if (grow > M - 1) grow = M - 1;                 \
            uint32_t doff = (uint32_t)((r * RS2 + q * 8) * 2);                   \
            cpasync16((SB) + AF_OFF + doff, Af + (size_t)grow * K + k0p + q * 8);\
        }                                                                        \
        {                                                                        \
            int r = tid >> 2, q = tid & 3;                                       \
            uint32_t doff = (uint32_t)((r * RS2 + q * 8) * 2);                   \
            cpasync16((SB) + BF_OFF + doff,                                      \
                      Wf + (size_t)(n0 + r) * K + k0p + q * 8);                  \
        }                                                                        \
        cpasync_commit();                                                        \
    }

    PREFETCHF(0, smbase);

    for (int kc = 0; kc < nchunk; kc++) {
        const uint32_t sb = smbase + ((kc & 1) ? STAGE_F : 0);
        if (kc + 1 < nchunk) {
            const uint32_t sbn = smbase + (((kc + 1) & 1) ? STAGE_F : 0);
            PREFETCHF(kc + 1, sbn);
            cpasync_wait<1>();
        } else {
            cpasync_wait<0>();
        }
        __syncthreads();

        #pragma unroll
        for (int s = 0; s < 2; s++) {
            uint32_t aF[2][4], bF[2][4];
            #pragma unroll
            for (int mt = 0; mt < 2; mt++) {
                uint32_t off = (uint32_t)((am_row + mt * 16) * (RS2 * 2)
                                          + s * 32 + am_colb);
                ldm_x4(sb + AF_OFF + off, aF[mt]);
            }
            #pragma unroll
            for (int np = 0; np < 2; np++) {
                uint32_t off = (uint32_t)((bn_row + np * 16) * (RS2 * 2)
                                          + s * 32 + bn_colb);
                ldm_x4(sb + BF_OFF + off, bF[np]);
            }
            #pragma unroll
            for (int mt = 0; mt < 2; mt++)
                #pragma unroll
                for (int nt = 0; nt < 4; nt++) {
                    uint32_t b0 = bF[nt >> 1][(nt & 1) * 2];
                    uint32_t b1 = bF[nt >> 1][(nt & 1) * 2 + 1];
                    mma_f16(acc[mt][nt], aF[mt], b0, b1);
                }
        }
        __syncthreads();
    }
    #undef PREFETCHF

    const int rbase = row0 + wm * 32 + (lane >> 2);
    const int cbase = n0 + wn * 32 + (lane & 3) * 2;
    #pragma unroll
    for (int mt = 0; mt < 2; mt++) {
        int r0 = rbase + mt * 16;
        int r1 = r0 + 8;
        float d0 = (r0 < M) ? g_dinv[r0] : 0.f;
        float d1 = (r1 < M) ? g_dinv[r1] : 0.f;
        #pragma unroll
        for (int nt = 0; nt < 4; nt++) {
            int c = cbase + nt * 8;
            if (r0 < M) {
                __half2 h = __floats2half2_rn(acc[mt][nt][0] * d0,
                                              acc[mt][nt][1] * d0);
                *(__half2*)(g_yh + (size_t)r0 * HDIM + c) = h;
            }
            if (r1 < M) {
                __half2 h = __floats2half2_rn(acc[mt][nt][2] * d1,
                                              acc[mt][nt][3] * d1);
                *(__half2*)(g_yh + (size_t)r1 * HDIM + c) = h;
            }
        }
    }
}

// -------- aggregation: gathers fp16 g_yh (8-way MLP), writes fp16 g_af --------
__global__ void __launch_bounds__(256)
k_aggr(const float* __restrict__ bias,
       const float* __restrict__ bng, const float* __restrict__ bnb,
       const float* __restrict__ bnm, const float* __restrict__ bnv,
       int do_bn, int n)
{
    int w = (blockIdx.x * blockDim.x + threadIdx.x) >> 5;
    if (w >= n) return;
    const int lane = threadIdx.x & 31;
    const int c = lane * 4;

    float4 acc;
    {
        uint2 v = *(const uint2*)(g_yh + (size_t)w * HDIM + c);
        float2 f0 = __half22float2(*(__half2*)&v.x);
        float2 f1 = __half22float2(*(__half2*)&v.y);
        acc.x = f0.x; acc.y = f0.y; acc.z = f1.x; acc.w = f1.y;
    }

    int e   = g_rowptr[w];
    int end = g_rowptr[w + 1];
    for (; e + 8 <= end; e += 8) {
        uint2 u[8];
        #pragma unroll
        for (int j = 0; j < 8; j++) {
            int cc = g_col[e + j];
            u[j] = *(const uint2*)(g_yh + (size_t)cc * HDIM + c);
        }
        #pragma unroll
        for (int j = 0; j < 8; j++) {
            float2 a = __half22float2(*(__half2*)&u[j].x);
            float2 b = __half22float2(*(__half2*)&u[j].y);
            acc.x += a.x; acc.y += a.y; acc.z += b.x; acc.w += b.y;
        }
    }
    for (; e + 4 <= end; e += 4) {
        uint2 u[4];
        #pragma unroll
        for (int j = 0; j < 4; j++) {
            int cc = g_col[e + j];
            u[j] = *(const uint2*)(g_yh + (size_t)cc * HDIM + c);
        }
        #pragma unroll
        for (int j = 0; j < 4; j++) {
            float2 a = __half22float2(*(__half2*)&u[j].x);
            float2 b = __half22float2(*(__half2*)&u[j].y);
            acc.x += a.x; acc.y += a.y; acc.z += b.x; acc.w += b.y;
        }
    }
    for (; e < end; e++) {
        int cc = g_col[e];
        uint2 u = *(const uint2*)(g_yh + (size_t)cc * HDIM + c);
        float2 a = __half22float2(*(__half2*)&u.x);
        float2 b = __half22float2(*(__half2*)&u.y);
        acc.x += a.x; acc.y += a.y; acc.z += b.x; acc.w += b.y;
    }

    const float dvw = g_dinv[w];
    float4 r;
    r.x = acc.x * dvw + bias[c + 0];
    r.y = acc.y * dvw + bias[c + 1];
    r.z = acc.z * dvw + bias[c + 2];
    r.w = acc.w * dvw + bias[c + 3];

    if (do_bn) {
        float i0 = rsqrtf(bnv[c + 0] + BN_EPS_F);
        float i1 = rsqrtf(bnv[c + 1] + BN_EPS_F);
        float i2 = rsqrtf(bnv[c + 2] + BN_EPS_F);
        float i3 = rsqrtf(bnv[c + 3] + BN_EPS_F);
        r.x = fmaxf((r.x - bnm[c + 0]) * i0 * bng[c + 0] + bnb[c + 0], 0.f);
        r.y = fmaxf((r.y - bnm[c + 1]) * i1 * bng[c + 1] + bnb[c + 1], 0.f);
        r.z = fmaxf((r.z - bnm[c + 2]) * i2 * bng[c + 2] + bnb[c + 2], 0.f);
        r.w = fmaxf((r.w - bnm[c + 3]) * i3 * bng[c + 3] + bnb[c + 3], 0.f);
    }

    __half2 h0 = __floats2half2_rn(r.x, r.y);
    __half2 h1 = __floats2half2_rn(r.z, r.w);
    uint2 o;
    o.x = *(uint32_t*)&h0;
    o.y = *(uint32_t*)&h1;
    *(uint2*)(g_af + (size_t)w * HDIM + c) = o;
}

// ---------------- fused pool + classifier: block g handles graph g ------------
__device__ __forceinline__ int lower_bound_idx(const void* b, int n, int key, int is64) {
    int lo = 0, hi = n;
    while (lo < hi) {
        int mid = (lo + hi) >> 1;
        int v = idx_at(b, mid, is64);
        if (v < key) lo = mid + 1; else hi = mid;
    }
    return lo;
}

__global__ void __launch_bounds__(256)
k_poolcls(const void* __restrict__ batch, int n,
          const float* __restrict__ Wc1, const float* __restrict__ bc1,
          const float* __restrict__ Wc2, const float* __restrict__ bc2,
          float* __restrict__ out)
{
    __shared__ float red[256];
    __shared__ float pooled[128];
    __shared__ float z[64];
    const int g = blockIdx.x;
    const int t = threadIdx.x;
    const int col  = t & 127;
    const int half = t >> 7;
    const int is64 = (g_not64 == 0);

    int start = lower_bound_idx(batch, n, g, is64);
    int end   = lower_bound_idx(batch, n, g + 1, is64);

    float a0 = 0.f, a1 = 0.f, a2 = 0.f, a3 = 0.f;
    int r = start + half;
    for (; r + 6 < end; r += 8) {
        a0 += __half2float(g_af[(size_t)r * HDIM + col]);
        a1 += __half2float(g_af[(size_t)(r + 2) * HDIM + col]);
        a2 += __half2float(g_af[(size_t)(r + 4) * HDIM + col]);
        a3 += __half2float(g_af[(size_t)(r + 6) * HDIM + col]);
    }
    for (; r < end; r += 2) a0 += __half2float(g_af[(size_t)r * HDIM + col]);
    red[t] = (a0 + a1) + (a2 + a3);
    __syncthreads();
    if (half == 0) {
        float cnt = (float)(end - start);
        pooled[col] = (red[t] + red[t + 128]) / fmaxf(cnt, 1.f);
    }
    __syncthreads();

    if (t < 64) {
        float s = bc1[t];
        #pragma unroll 8
        for (int k = 0; k < HDIM; k++)
            s = fmaf(pooled[k], Wc1[k * 64 + t], s);
        z[t] = fmaxf(s, 0.f);
    }
    __syncthreads();

    if (t < 16) {
        float s = bc2[t];
        #pragma unroll
        for (int k = 0; k < 64; k++)
            s = fmaf(z[k], Wc2[k * 16 + t], s);
        out[g * 16 + t] = s;
    }
}

// ---------------- launch -------------------------------------------------------
extern "C" void kernel_launch(void* const* d_in, const int* in_sizes, int n_in,
                              void* d_out, int out_size)
{
    const float* x     = (const float*)d_in[0];
    const void*  ei    = d_in[1];
    const void*  batch = d_in[2];
    const float* W1  = (const float*)d_in[3];
    const float* b1  = (const float*)d_in[4];
    const float* W2  = (const float*)d_in[5];
    const float* b2  = (const float*)d_in[6];
    const float* W3  = (const float*)d_in[7];
    const float* b3  = (const float*)d_in[8];
    const float* bn1g = (const float*)d_in[9];
    const float* bn1b = (const float*)d_in[10];
    const float* bn1m = (const float*)d_in[11];
    const float* bn1v = (const float*)d_in[12];
    const float* bn2g = (const float*)d_in[13];
    const float* bn2b = (const float*)d_in[14];
    const float* bn2m = (const float*)d_in[15];
    const float* bn2v = (const float*)d_in[16];
    const float* Wc1 = (const float*)d_in[17];
    const float* bc1 = (const float*)d_in[18];
    const float* Wc2 = (const float*)d_in[19];
    const float* bc2 = (const float*)d_in[20];

    const int n = in_sizes[2];
    const int e = in_sizes[1] / 2;
    const int K1 = in_sizes[0] / n;     // 256
    const int nb = (n + SCAN_BLK - 1) / SCAN_BLK;

    cudaFuncSetAttribute(k_gemm_bf16,
                         cudaFuncAttributeMaxDynamicSharedMemorySize, GEMM_SMEM);
    cudaFuncSetAttribute(k_gemm_f16<2>,
                         cudaFuncAttributeMaxDynamicSharedMemorySize, GEMM_SMEM_F);
    cudaFuncSetAttribute(k_gemm_f16<3>,
                         cudaFuncAttributeMaxDynamicSharedMemorySize, GEMM_SMEM_F);

    const int gblk = (n + 127) / 128;
    const int ablk = ((n * 32) + 255) / 256;
    dim3 ggrid(gblk, 2);

    int nwords = in_sizes[1];
    if (nwords > 16384) nwords = 16384;
    int init_items = n > (nwords + 1) / 2 ? n : (nwords + 1) / 2;

    const int fblk = (e + 255) / 256;
    const int tot_s = n * K1 / 8 + K1 * 32 + 2 * HDIM * 32;
    const int sblk = (tot_s + 255) / 256;

    // 12 launches total
    k_init<<<(init_items + 255) / 256, 256>>>((const unsigned*)ei, nwords, n); // 0
    k_hist<<<(e + 255) / 256, 256>>>(ei, e);                                   // 1
    k_scan1<<<nb, SCAN_BLK>>>(n);                                              // 2
    k_scan23<<<(n + 255) / 256, 256>>>(nb, n);                                 // 3
    k_prep<<<fblk + sblk, 256>>>(ei, e, fblk, x, W1, W2, W3, n, K1);           // 4
    // conv1
    k_gemm_bf16<<<ggrid, 256, GEMM_SMEM>>>(n, K1);                             // 5
    k_aggr<<<ablk, 256>>>(b1, bn1g, bn1b, bn1m, bn1v, 1, n);                   // 6
    // conv2
    k_gemm_f16<2><<<ggrid, 256, GEMM_SMEM_F>>>(n);                             // 7
    k_aggr<<<ablk, 256>>>(b2, bn2g, bn2b, bn2m, bn2v, 1, n);                   // 8
    // conv3
    k_gemm_f16<3><<<ggrid, 256, GEMM_SMEM_F>>>(n);                             // 9
    k_aggr<<<ablk, 256>>>(b3, bn1g, bn1b, bn1m, bn1v, 0, n);                   // 10
    // fused pool + classifier
    k_poolcls<<<NG, 256>>>(batch, n, Wc1, bc1, Wc2, bc2, (float*)d_out);       // 11
}